// round 1
// baseline (speedup 1.0000x reference)
#include <cuda_runtime.h>
#include <cuda_bf16.h>

// AdEx neuron simulation, sm_103a.
// Layout: one thread per neuron, T-loop in-kernel, state (v, c, ref) in registers.
// I reads and v writes are coalesced along N (the fast axis of [T, N]).
// Software-pipelined: prefetch next UNROLL rows of I while computing current group.

#define UNROLL 4

__global__ void __launch_bounds__(256) adex_kernel(
    const float* __restrict__ I,    // [T, N]
    const float* __restrict__ v0,   // [N]
    const float* __restrict__ c0,   // [N]
    const int*   __restrict__ ref0, // [N]
    float*       __restrict__ out,  // [T, N]
    int T, int N)
{
    int n = blockIdx.x * blockDim.x + threadIdx.x;
    if (n >= N) return;

    // Constants (folded from the reference module)
    const float EL       = -70.6e-3f;
    const float VT       = -50.4e-3f;
    const float INV_DELT = 500.0f;                 // 1 / DELTAT
    const float GLDT     = 6.0e-11f;               // GL * DELTAT
    const float GL       = 30.0e-9f;
    const float DT_CM    = 3.5587188612099645e6f;  // DT / CM
    const float DT_TAUW  = 6.944444444444445e-3f;  // DT / TAUW
    const float Acst     = 4.0e-9f;
    const float Bcst     = 0.0805e-9f;
    const int   REF_STEPS = 2;

    float v   = v0[n];
    float c   = c0[n];
    int   ref = ref0[n];

    const float* Ip = I + n;
    float*       Op = out + n;

    // Prime the pipeline: first UNROLL rows of I
    float buf[UNROLL];
    #pragma unroll
    for (int u = 0; u < UNROLL; ++u) {
        int tt = u;
        buf[u] = (tt < T) ? __ldcs(Ip + (long)tt * N) : 0.0f;
    }

    for (int t = 0; t < T; t += UNROLL) {
        // Prefetch next group while we compute this one (MLP = UNROLL)
        float nbuf[UNROLL];
        #pragma unroll
        for (int u = 0; u < UNROLL; ++u) {
            int tt = t + UNROLL + u;
            nbuf[u] = (tt < T) ? __ldcs(Ip + (long)tt * N) : 0.0f;
        }

        #pragma unroll
        for (int u = 0; u < UNROLL; ++u) {
            int tt = t + u;
            if (tt < T) {
                float It     = buf[u];
                bool  in_ref = ref > 0;
                float v_eff  = in_ref ? EL : v;

                // AdEx membrane dynamics (forward Euler), exp arg clipped at 15
                float arg = fminf((v_eff - VT) * INV_DELT, 15.0f);
                float ex  = GLDT * expf(arg);
                float dv  = DT_CM * (-GL * (v_eff - EL) + ex - c + It);
                float v_new = in_ref ? EL : (v_eff + dv);

                // adaptation current
                float c_new = c + DT_TAUW * (Acst * (v_eff - EL) - c);

                // spike detection + reset
                bool spike = v_new >= VT;
                v   = spike ? EL : v_new;
                c   = spike ? (c_new + Bcst) : c_new;
                ref = spike ? REF_STEPS : max(ref - 1, 0);

                __stcs(Op + (long)tt * N, v);
            }
        }

        #pragma unroll
        for (int u = 0; u < UNROLL; ++u) buf[u] = nbuf[u];
    }
}

extern "C" void kernel_launch(void* const* d_in, const int* in_sizes, int n_in,
                              void* d_out, int out_size)
{
    const float* I    = (const float*)d_in[0];
    const float* v0   = (const float*)d_in[1];
    const float* c0   = (const float*)d_in[2];
    const int*   ref0 = (const int*)  d_in[3];
    float*       out  = (float*)d_out;

    int N = in_sizes[1];            // v0 has N elements
    int T = in_sizes[0] / N;        // I has T*N elements

    int threads = 256;
    int blocks  = (N + threads - 1) / threads;
    adex_kernel<<<blocks, threads>>>(I, v0, c0, ref0, out, T, N);
}